// round 16
// baseline (speedup 1.0000x reference)
#include <cuda_runtime.h>
#include <cuda_fp16.h>
#include <cstdint>

#define NNODES  50000
#define HID     128
#define NREL    9
#define NEDGES  600000
#define RNBUCK  (NREL * NNODES)
#define CAP     32
#define WTOT    (3 * NREL * HID * HID)
#define HTOT    (NNODES * HID)                 // 6.4M
#define INITN   HTOT                           // covers WTOT and RNBUCK too

#define MTILE   128
#define NROWPAD 50048                          // 391 * 128
#define GRID_M  (NROWPAD / MTILE)              // 391

#define NSTAGE  5
#define KSLICE  64
#define PIT     72                             // smem row pitch in halves
#define AS_ELE  (MTILE * PIT)
#define AS_BYTES (AS_ELE * 2)
#define NSLICE  (NREL * 2)                     // 18 K-slices of 64

// ---------------- scratch (device globals; no allocation) ----------------
__device__ int    g_counts[RNBUCK];
__device__ int    g_bucket[(size_t)RNBUCK * CAP];                  // 57.6 MB
__device__ __align__(256) __half g_Hh[3][HTOT];                    // fp16 emb/H1/H2
__device__ __align__(256) __half g_Wb[WTOT];                       // W in MMA-fragment order
__device__ __align__(256) __half g_Y[(size_t)NREL * NROWPAD * HID]; // 115 MB fp16

// ---------------- helpers ----------------
__device__ __forceinline__ void mma_f16(float& c0, float& c1, float& c2, float& c3,
                                        uint32_t a0, uint32_t a1, uint32_t a2, uint32_t a3,
                                        uint32_t b0, uint32_t b1) {
    asm volatile(
        "mma.sync.aligned.m16n8k16.row.col.f32.f16.f16.f32 "
        "{%0,%1,%2,%3}, {%4,%5,%6,%7}, {%8,%9}, {%0,%1,%2,%3};\n"
        : "+f"(c0), "+f"(c1), "+f"(c2), "+f"(c3)
        : "r"(a0), "r"(a1), "r"(a2), "r"(a3), "r"(b0), "r"(b1));
}
__device__ __forceinline__ void ldm_x4(uint32_t* r, uint32_t addr) {
    asm volatile("ldmatrix.sync.aligned.m8n8.x4.shared.b16 {%0,%1,%2,%3}, [%4];"
                 : "=r"(r[0]), "=r"(r[1]), "=r"(r[2]), "=r"(r[3]) : "r"(addr));
}
__device__ __forceinline__ void cp16(uint32_t sdst, const void* gsrc) {
    asm volatile("cp.async.cg.shared.global [%0], [%1], 16;\n"
                 :: "r"(sdst), "l"(gsrc) : "memory");
}
__device__ __forceinline__ void cp_commit() {
    asm volatile("cp.async.commit_group;\n" ::: "memory");
}
__device__ __forceinline__ void cp_wait() {      // NSTAGE-1 = 4
    asm volatile("cp.async.wait_group 4;\n" ::: "memory");
}

// ---------------- init: zero counts + fragment-order fp16 W + fp16 emb ------
// Output blob index (halves): ((((mat*2+ks)*4+kki)*4+ntp)*2+wn)*256 + lane*8 + h
// holds W[mat][k][n] with  g=lane>>2, tg=lane&3, ntl=h>>2, reg=(h>>1)&1, e=h&1,
//   n = wn*64 + (ntp*2+ntl)*8 + g
//   k = ks*64 + kki*16 + reg*8 + tg*2 + e
// so one LDG.128 per (slice,kki,ntp) gives {b0,b1} for two adjacent n-tiles.
__global__ void k_init(const float* __restrict__ W, const float* __restrict__ emb) {
    int i = blockIdx.x * blockDim.x + threadIdx.x;
    if (i < WTOT) {
        int h    = i & 7;
        int lane = (i >> 3) & 31;
        int wn   = (i >> 8) & 1;
        int ntp  = (i >> 9) & 3;
        int kki  = (i >> 11) & 3;
        int ks   = (i >> 13) & 1;
        int mat  = i >> 14;
        int g = lane >> 2, tg = lane & 3;
        int ntl = h >> 2;
        int reg = (h >> 1) & 1;
        int e   = h & 1;
        int n = wn * 64 + (ntp * 2 + ntl) * 8 + g;
        int k = ks * 64 + kki * 16 + reg * 8 + tg * 2 + e;
        g_Wb[i] = __float2half_rn(W[(mat << 14) + k * HID + n]);
    }
    if (i < RNBUCK) g_counts[i] = 0;
    if (i < HTOT)   g_Hh[0][i] = __float2half_rn(emb[i]);
}

// ---------------- bucket scatter ----------------
__global__ void k_bucket(const int* __restrict__ dest, const int* __restrict__ etype,
                         const int* __restrict__ src) {
    int e = blockIdx.x * blockDim.x + threadIdx.x;
    if (e < NEDGES) {
        int key = etype[e] * NNODES + dest[e];
        int pos = atomicAdd(&g_counts[key], 1);
        if (pos < CAP) g_bucket[(size_t)key * CAP + pos] = src[e];
    }
}

// ---------------- gather: Y[r][n][:] = (half)( inv_s * sum_{src} Hh[src] ) --
// grid (391, 9), 256 threads. Each warp owns 16 dest rows of one relation.
__global__ void __launch_bounds__(256)
k_gather(const __half* __restrict__ Hin, float inv_s) {
    const int lane = threadIdx.x & 31;
    const int wid  = threadIdx.x >> 5;
    const int r    = blockIdx.y;
    const int d0   = blockIdx.x * MTILE + wid * 16;
    const int mycol = lane * 4;                   // halves index
    __half* Yg = g_Y + (size_t)r * NROWPAD * HID;

    int cnt = 0;
    {
        int dd = d0 + lane;
        if (lane < 16 && dd < NNODES) {
            cnt = g_counts[r * NNODES + dd];
            if (cnt > CAP) cnt = CAP;
        }
    }
    int x = cnt;
    #pragma unroll
    for (int o = 1; o < 32; o <<= 1) {
        int y = __shfl_up_sync(0xffffffffu, x, o);
        if (lane >= o) x += y;
    }
    const int excl  = x - cnt;
    const int total = __shfl_sync(0xffffffffu, excl, 16);

    float4 acc = make_float4(0.f, 0.f, 0.f, 0.f);
    int cur = 0;
    int nextb = __shfl_sync(0xffffffffu, excl, 1);

    #define FLUSH() do { \
        __half2 h0 = __floats2half2_rn(acc.x * inv_s, acc.y * inv_s); \
        __half2 h1 = __floats2half2_rn(acc.z * inv_s, acc.w * inv_s); \
        uint2 o_; o_.x = *(uint32_t*)&h0; o_.y = *(uint32_t*)&h1; \
        __stcs((uint2*)(Yg + (size_t)(d0 + cur) * HID + mycol), o_); \
        acc.x = acc.y = acc.z = acc.w = 0.f; \
        cur++; \
        int nb2 = __shfl_sync(0xffffffffu, excl, (cur < 16) ? (cur + 1) : 16); \
        nextb = (cur < 16) ? nb2 : 0x7fffffff; \
    } while (0)

    for (int ib = 0; ib < total; ib += 32) {
        int rem = total - ib; if (rem > 32) rem = 32;
        const int j = ib + lane;

        int row = -1;
        #pragma unroll
        for (int i = 0; i < 16; i++) {
            int p = __shfl_sync(0xffffffffu, excl, i);
            row += (p <= j) ? 1 : 0;
        }
        if (row < 0) row = 0;
        if (row > 15) row = 15;
        int rowExcl = __shfl_sync(0xffffffffu, excl, row);
        int slot = j - rowExcl;
        if (slot < 0) slot = 0;
        if (slot >= CAP) slot = CAP - 1;

        int sv = 0;
        if (lane < rem)
            sv = g_bucket[(size_t)(r * NNODES + d0 + row) * CAP + slot];

        int jj = 0;
        while (jj < rem) {
            int nb = rem - jj; if (nb > 8) nb = 8;
            uint2 v[8];
            #pragma unroll
            for (int u = 0; u < 8; u++) {
                if (u < nb) {
                    int s = __shfl_sync(0xffffffffu, sv, jj + u);
                    v[u] = *(const uint2*)(Hin + (size_t)s * HID + mycol);
                }
            }
            #pragma unroll
            for (int u = 0; u < 8; u++) {
                if (u < nb) {
                    int idx = ib + jj + u;
                    while (idx >= nextb) FLUSH();
                    float2 f0 = __half22float2(*(__half2*)&v[u].x);
                    float2 f1 = __half22float2(*(__half2*)&v[u].y);
                    acc.x += f0.x; acc.y += f0.y;
                    acc.z += f1.x; acc.w += f1.y;
                }
            }
            jj += nb;
        }
    }
    while (cur < 16) FLUSH();
    #undef FLUSH
}

// ---------------- GEMM: H = relu( s * sum_r Y_r @ W_r + cnt_r * b_r ) -------
// fp16 m16n8k16, fp32 accum. A: 5-stage cp.async + ldmatrix.
// B: direct LDG.128 from fragment-ordered W blob (L2-resident, no smem).
struct GSMem {
    __half A[NSTAGE][AS_ELE];    // 5 x 18 KB
    float bias[NREL * HID];      // 4.5 KB
};

__global__ void __launch_bounds__(256, 2)
k_gemm(const __half* __restrict__ Y, const __half* __restrict__ Wb_l,
       const float* __restrict__ Bv, float* __restrict__ HoutF,
       __half* __restrict__ HoutH, int relu, float scale, float out_inv) {
    extern __shared__ __align__(16) char smraw[];
    GSMem* sm = (GSMem*)smraw;

    const int tid  = threadIdx.x;
    const int lane = tid & 31;
    const int wid  = tid >> 5;
    const int base = blockIdx.x * MTILE;

    for (int i = tid; i < NREL * HID; i += 256) sm->bias[i] = Bv[i];

    const uint32_t sA0 = (uint32_t)__cvta_generic_to_shared(&sm->A[0][0]);

    // issue A K-slice s into stage st: 128 rows x 64 halves (128B = 8 cp16)
    #define ISSUE(s_, st_) do { \
        const int r_  = (s_) >> 1; \
        const int ks_ = (s_) & 1; \
        const __half* Ag = Y + ((size_t)r_ * NROWPAD + base) * HID + ks_ * KSLICE; \
        const uint32_t sa = sA0 + (st_) * AS_BYTES; \
        _Pragma("unroll") \
        for (int u = 0; u < 4; u++) { \
            int j = tid + 256 * u; \
            int row = j >> 3, seg = j & 7; \
            cp16(sa + (row * PIT + seg * 8) * 2, Ag + (size_t)row * HID + seg * 8); \
        } \
        cp_commit(); \
    } while (0)

    ISSUE(0, 0); ISSUE(1, 1); ISSUE(2, 2); ISSUE(3, 3); ISSUE(4, 4);

    const int wm    = wid & 3;
    const int wn    = wid >> 2;           // n half: cols [wn*64, +64)
    const int wncol = wn * 64;

    const int rowA = wm * 32 + (lane & 7) + ((lane >> 3) & 1) * 8;
    const int kA   = (lane >> 4) * 8;

    float c[2][8][4];
    #pragma unroll
    for (int m2 = 0; m2 < 2; m2++)
        #pragma unroll
        for (int nt = 0; nt < 8; nt++)
            #pragma unroll
            for (int j = 0; j < 4; j++) c[m2][nt][j] = 0.0f;

    // W blob: per (slice, kki, ntp): uint4 at index ((s*4+kki)*4+ntp)*64 + wn*32 + lane
    const uint4* wq = (const uint4*)Wb_l + wn * 32 + lane;

    for (int s = 0; s < NSLICE; s++) {
        const int st = s % NSTAGE;
        cp_wait();
        __syncthreads();

        const uint32_t aBase = sA0 + st * AS_BYTES + (rowA * PIT + kA) * 2;

        #pragma unroll
        for (int kki = 0; kki < 4; kki++) {
            const int kk = kki * 16;
            uint32_t a[2][4];
            ldm_x4(a[0], aBase + kk * 2);
            ldm_x4(a[1], aBase + (16 * PIT + kk) * 2);
            const uint4* wk = wq + (size_t)((s * 4 + kki) * 4) * 64;
            #pragma unroll
            for (int ntp = 0; ntp < 4; ntp++) {
                const uint4 bv = __ldg(wk + ntp * 64);
                const int nt0 = ntp * 2;
                mma_f16(c[0][nt0][0], c[0][nt0][1], c[0][nt0][2], c[0][nt0][3],
                        a[0][0], a[0][1], a[0][2], a[0][3], bv.x, bv.y);
                mma_f16(c[1][nt0][0], c[1][nt0][1], c[1][nt0][2], c[1][nt0][3],
                        a[1][0], a[1][1], a[1][2], a[1][3], bv.x, bv.y);
                mma_f16(c[0][nt0+1][0], c[0][nt0+1][1], c[0][nt0+1][2], c[0][nt0+1][3],
                        a[0][0], a[0][1], a[0][2], a[0][3], bv.z, bv.w);
                mma_f16(c[1][nt0+1][0], c[1][nt0+1][1], c[1][nt0+1][2], c[1][nt0+1][3],
                        a[1][0], a[1][1], a[1][2], a[1][3], bv.z, bv.w);
            }
        }
        __syncthreads();
        if (s + NSTAGE < NSLICE) ISSUE(s + NSTAGE, st);
    }
    #undef ISSUE

    // ---- epilogue: rescale, bias via per-row true counts, relu, store ----
    const int g  = lane >> 2;
    const int tg = lane & 3;
    #pragma unroll
    for (int m2 = 0; m2 < 2; m2++) {
        #pragma unroll
        for (int h = 0; h < 2; h++) {
            const int row = wm * 32 + m2 * 16 + h * 8 + g;
            const int d = base + row;
            if (d >= NNODES) continue;
            float cnt[NREL];
            #pragma unroll
            for (int r = 0; r < NREL; r++)
                cnt[r] = (float)g_counts[r * NNODES + d];
            #pragma unroll
            for (int nt = 0; nt < 8; nt++) {
                const int col0 = wncol + nt * 8 + tg * 2;
                float v0 = c[m2][nt][h * 2 + 0] * scale;
                float v1 = c[m2][nt][h * 2 + 1] * scale;
                #pragma unroll
                for (int r = 0; r < NREL; r++) {
                    const float cc = cnt[r];
                    v0 += cc * sm->bias[r * HID + col0];
                    v1 += cc * sm->bias[r * HID + col0 + 1];
                }
                if (relu) { v0 = fmaxf(v0, 0.f); v1 = fmaxf(v1, 0.f); }
                if (HoutH) {
                    __half2 p = __floats2half2_rn(v0 * out_inv, v1 * out_inv);
                    *(__half2*)(HoutH + (size_t)d * HID + col0) = p;
                } else {
                    HoutF[(size_t)d * HID + col0]     = v0;
                    HoutF[(size_t)d * HID + col0 + 1] = v1;
                }
            }
        }
    }
}

// ---------------- launch ----------------------------------------------------
extern "C" void kernel_launch(void* const* d_in, const int* in_sizes, int n_in,
                              void* d_out, int out_size) {
    const int*   eidx  = (const int*)d_in[0];      // [2, NEDGES]: row0=dest, row1=src
    const int*   etype = (const int*)d_in[1];
    const float* emb   = (const float*)d_in[2];
    const float* wts   = (const float*)d_in[3];    // [3, NREL, HID, HID]
    const float* bias  = (const float*)d_in[4];    // [3, NREL, HID]
    float*       out   = (float*)d_out;

    const int* dest = eidx;
    const int* src  = eidx + NEDGES;

    __half* hh = nullptr;
    cudaGetSymbolAddress((void**)&hh, g_Hh);
    __half* hh0 = hh;                      // fp16 emb
    __half* hh1 = hh + (size_t)HTOT;       // H1          (scale 1)
    __half* hh2 = hh + (size_t)2 * HTOT;   // H2 * 2^-11
    __half* wb = nullptr;
    cudaGetSymbolAddress((void**)&wb, g_Wb);
    __half* yb = nullptr;
    cudaGetSymbolAddress((void**)&yb, g_Y);

    k_init<<<(INITN + 255) / 256, 256>>>(wts, emb);
    k_bucket<<<(NEDGES + 255) / 256, 256>>>(dest, etype, src);

    const int smem_sz = (int)sizeof(GSMem);
    static_assert(sizeof(GSMem) <= 113 * 1024, "gemm smem too big for 2 blocks/SM");
    cudaFuncSetAttribute(k_gemm, cudaFuncAttributeMaxDynamicSharedMemorySize, smem_sz);

    const size_t wstride = (size_t)NREL * HID * HID;   // 147456 halves per layer blob
    const size_t bstride = (size_t)NREL * HID;
    dim3 ggrid(GRID_M, NREL);

    // Exact power-of-2 scaling chain (fp16 range safety, worst-case bounds):
    //  L1: Y1 = A1 (<=32*1)            gemm*1      -> H1 fp16 (<=844)
    //  L2: Y2 = A2 * 2^-6 (<=422)      gemm*2^6    -> H2*2^-11 fp16 (<=3e4 bound)
    //  L3: Y3 = A3 * 2^-11 * 2^-5      gemm*2^16   -> fp32 out
    k_gather<<<ggrid, 256>>>(hh0, 1.0f);
    k_gemm<<<GRID_M, 256, smem_sz>>>(yb, wb, bias, nullptr, hh1, 1,
                                     1.0f, 1.0f);
    k_gather<<<ggrid, 256>>>(hh1, 1.0f / 64.0f);
    k_gemm<<<GRID_M, 256, smem_sz>>>(yb, wb + wstride, bias + bstride, nullptr, hh2, 1,
                                     64.0f, 1.0f / 2048.0f);
    k_gather<<<ggrid, 256>>>(hh2, 1.0f / 32.0f);
    k_gemm<<<GRID_M, 256, smem_sz>>>(yb, wb + 2 * wstride, bias + 2 * bstride, out, nullptr, 0,
                                     65536.0f, 1.0f);
}